// round 8
// baseline (speedup 1.0000x reference)
#include <cuda_runtime.h>
#include <cuda_fp16.h>
#include <cstdint>

// GRU decoder, H=4096, T=2048. Persistent single kernel + software grid barrier.
// R2: fp16 weight scratch (100.7 MB) -> L2-resident working set.
// R6: compiler-batched loads + fast approx gates + deferred Stage-B. [25.40 ms]
// R7 lesson: cp.async ring = less MLP than register batching -> reverted.
// R8: O(1)-arrival grid barrier: per-block padded flag (st.release, parallel)
//     + block-0 aggregation (152 threads poll 1 flag each) + gen broadcast.
//     Replaces 152 serialized atomicAdds (~4-5K cyc/step) with ~1.2K cyc.

#define HDIM 4096
#define IN_DIM 400
#define OROWS 401
#define NOUT 400
#define WARPS_PER_BLOCK 28
#define NTHREADS (WARPS_PER_BLOCK * 32)
#define MAXBLK 256

__device__ __half g_whh_h[(size_t)3 * HDIM * HDIM];   // 100.7 MB fp16 W_hh
__device__ __half g_wout_h[(size_t)OROWS * HDIM];     // 3.3 MB fp16 W_out
__device__ float g_h[2][HDIM];                        // double-buffered hidden state
__device__ float g_gx[3 * HDIM];                      // W_ih @ relu(x) + b_ih
__device__ unsigned g_flags[MAXBLK * 32];             // per-block arrive flags, 128B apart
__device__ unsigned g_gen;                            // release generation (monotonic)

__device__ __forceinline__ float warp_sum(float v) {
#pragma unroll
    for (int o = 16; o; o >>= 1) v += __shfl_xor_sync(0xffffffffu, v, o);
    return v;
}

__device__ __forceinline__ void st_release(unsigned* p, unsigned v) {
    asm volatile("st.global.release.gpu.u32 [%0], %1;" :: "l"(p), "r"(v) : "memory");
}
__device__ __forceinline__ unsigned ld_acquire(const unsigned* p) {
    unsigned v;
    asm volatile("ld.global.acquire.gpu.u32 %0, [%1];" : "=r"(v) : "l"(p) : "memory");
    return v;
}

// Flag barrier. All blocks co-resident (grid == #SMs, 1 blk/SM).
// target strictly increases per call and across graph replays.
__device__ __forceinline__ void grid_sync_flag(unsigned target) {
    __syncthreads();                       // all my block's work done
    if (blockIdx.x == 0) {
        // threads 1..gridDim.x-1 each poll one peer's flag (parallel)
        unsigned tid = threadIdx.x;
        if (tid >= 1 && tid < gridDim.x) {
            while ((int)(ld_acquire(&g_flags[tid * 32]) - target) < 0) { }
        }
        __syncthreads();                   // all flags observed
        if (tid == 0) {
            __threadfence();
            st_release(&g_gen, target);    // release everyone
        }
        // block 0 proceeds immediately (it observed all arrivals itself)
    } else {
        if (threadIdx.x == 0) {
            __threadfence();
            st_release(&g_flags[blockIdx.x * 32], target);  // parallel arrival
            while ((int)(ld_acquire(&g_gen) - target) < 0) { }
        }
        __syncthreads();
    }
}

// fast gates: |err| ~1e-5, negligible vs fp16 weight quantization (2.8e-4)
__device__ __forceinline__ float fast_sigmoid(float x) {
    float e;
    asm("ex2.approx.f32 %0, %1;" : "=f"(e) : "f"(-1.4426950408889634f * x));
    float r;
    asm("rcp.approx.f32 %0, %1;" : "=f"(r) : "f"(1.0f + e));
    return r;
}
__device__ __forceinline__ float fast_tanh(float x) {
    float r;
    asm("tanh.approx.f32 %0, %1;" : "=f"(r) : "f"(x));
    return r;
}

// dot of 8 fp16 weights (as uint4) with 8 fp32 h values, fp32 accumulate
__device__ __forceinline__ float dot8(uint4 u, float4 hA, float4 hB) {
    float2 p; float s0 = 0.f, s1 = 0.f;
    p = __half22float2(*(const __half2*)&u.x); s0 += p.x * hA.x; s1 += p.y * hA.y;
    p = __half22float2(*(const __half2*)&u.y); s0 += p.x * hA.z; s1 += p.y * hA.w;
    p = __half22float2(*(const __half2*)&u.z); s0 += p.x * hB.x; s1 += p.y * hB.y;
    p = __half22float2(*(const __half2*)&u.w); s0 += p.x * hB.z; s1 += p.y * hB.w;
    return s0 + s1;
}

__global__ void __launch_bounds__(NTHREADS, 1)
decoder_persistent_kernel(const float* __restrict__ start,
                          const float* __restrict__ enc,
                          const float* __restrict__ W_ih,
                          const float* __restrict__ W_hh,
                          const float* __restrict__ b_ih,
                          const float* __restrict__ b_hh,
                          const float* __restrict__ W_out,
                          const float* __restrict__ b_out,
                          const int*   __restrict__ maxlen_ptr,
                          float* __restrict__ out)
{
    __shared__ float h_s[HDIM];

    const int lane   = threadIdx.x & 31;
    const int warp   = threadIdx.x >> 5;
    const int gwarp  = blockIdx.x * WARPS_PER_BLOCK + warp;
    const int gwarps = gridDim.x * WARPS_PER_BLOCK;
    const int gtid    = blockIdx.x * NTHREADS + threadIdx.x;
    const int gthreads = gridDim.x * NTHREADS;
    const int T = maxlen_ptr ? *maxlen_ptr : 2048;

    // barrier generation base: read BEFORE any flag of this launch can be set
    // (block 0 can only advance g_gen after every block publishes flag #1,
    //  which happens after that block's threads all read the base). Monotonic
    //  across graph replays -> deterministic, no reset needed.
    const unsigned gen_base = ld_acquire(&g_gen);
    unsigned bar = gen_base;

    // ---- convert W_hh, W_out to fp16 scratch (every launch; deterministic) ----
    {
        const size_t total = (size_t)3 * HDIM * HDIM;
        for (size_t idx = (size_t)gtid * 4; idx < total; idx += (size_t)gthreads * 4) {
            float4 v = *(const float4*)(W_hh + idx);
            __half2* dst = (__half2*)(g_whh_h + idx);
            dst[0] = __floats2half2_rn(v.x, v.y);
            dst[1] = __floats2half2_rn(v.z, v.w);
        }
        const size_t ototal = (size_t)OROWS * HDIM;
        for (size_t idx = (size_t)gtid * 4; idx < ototal; idx += (size_t)gthreads * 4) {
            float4 v = *(const float4*)(W_out + idx);
            __half2* dst = (__half2*)(g_wout_h + idx);
            dst[0] = __floats2half2_rn(v.x, v.y);
            dst[1] = __floats2half2_rn(v.z, v.w);
        }
    }

    // ---- init: h0 = encoder_hidden ----
    for (int idx = gtid; idx < HDIM; idx += gthreads)
        g_h[0][idx] = enc[idx];

    // ---- gx = W_ih @ relu(start) + b_ih (once per launch, fp32) ----
    for (int r = gwarp; r < 3 * HDIM; r += gwarps) {
        const float* wr = W_ih + (size_t)r * IN_DIM;
        float acc = 0.f;
        for (int k = lane; k < IN_DIM; k += 32) {
            float x = start[k];
            x = x > 0.f ? x : 0.f;
            acc += wr[k] * x;
        }
        acc = warp_sum(acc);
        if (lane == 0) g_gx[r] = acc + b_ih[r];
    }
    grid_sync_flag(++bar);

    // Stage-B row mapping: spread 401 W_out rows evenly across all SMs
    int spread = gwarps / OROWS;
    if (spread < 1) spread = 1;
    int brow = -1;
    if ((gwarp % spread) == 0 && (gwarp / spread) < OROWS) brow = gwarp / spread;

    // my Stage-A row (fixed for the whole launch; <= 1 row per warp)
    const int myrow = (gwarp < HDIM) ? gwarp : -1;

    // hoist per-row constants out of the time loop
    float c_br = 0.f, c_bz = 0.f, c_bn = 0.f, c_gr = 0.f, c_gz = 0.f, c_gn = 0.f;
    if (myrow >= 0) {
        c_br = b_hh[myrow];
        c_bz = b_hh[myrow + HDIM];
        c_bn = b_hh[myrow + 2 * HDIM];
        c_gr = g_gx[myrow];
        c_gz = g_gx[myrow + HDIM];
        c_gn = g_gx[myrow + 2 * HDIM];
    }
    const float c_bo = (brow >= 0) ? b_out[brow] : 0.f;

    // ---- main recurrence ----
    for (int t = 0; t < T; t++) {
        const float* __restrict__ hc = g_h[t & 1];
        float* __restrict__ hn = g_h[(t + 1) & 1];

        // stage h_cur into shared memory (vectorized, fully coalesced)
        {
            const float4* src = (const float4*)hc;
            float4* dst = (float4*)h_s;
            for (int idx = threadIdx.x; idx < HDIM / 4; idx += NTHREADS)
                dst[idx] = src[idx];
        }
        __syncthreads();

        // Stage A: one warp per output i; compiler-scheduled batched loads
        if (myrow >= 0) {
            const int i = myrow;
            const uint4* w0 = (const uint4*)(g_whh_h + (size_t)i * HDIM);
            const uint4* w1 = (const uint4*)(g_whh_h + ((size_t)i + HDIM) * HDIM);
            const uint4* w2 = (const uint4*)(g_whh_h + ((size_t)i + 2 * HDIM) * HDIM);
            const float4* h4 = (const float4*)h_s;
            float a0 = 0.f, a1 = 0.f, a2 = 0.f;
#pragma unroll 8
            for (int k = lane; k < HDIM / 8; k += 32) {   // 16 iterations
                uint4 u0 = w0[k];
                uint4 u1 = w1[k];
                uint4 u2 = w2[k];
                float4 hA = h4[2 * k];
                float4 hB = h4[2 * k + 1];
                a0 += dot8(u0, hA, hB);
                a1 += dot8(u1, hA, hB);
                a2 += dot8(u2, hA, hB);
            }
            a0 = warp_sum(a0);
            a1 = warp_sum(a1);
            a2 = warp_sum(a2);
            float r = fast_sigmoid(c_gr + a0 + c_br);
            float z = fast_sigmoid(c_gz + a1 + c_bz);
            float n = fast_tanh(c_gn + r * (a2 + c_bn));
            if (lane == 0) {
                hn[i] = (1.f - z) * n + z * h_s[i];
            }
        }

        // Stage B (deferred, for step t-1): h_new(t-1) == h_s; pre-barrier.
        if (t > 0 && brow >= 0) {
            const uint4* wr = (const uint4*)(g_wout_h + (size_t)brow * HDIM);
            const float4* h4 = (const float4*)h_s;
            float acc = 0.f;
#pragma unroll 4
            for (int k = lane; k < HDIM / 8; k += 32) {
                uint4 u = wr[k];
                acc += dot8(u, h4[2 * k], h4[2 * k + 1]);
            }
            acc = warp_sum(acc);
            if (lane == 0) {
                float o = acc + c_bo;
                int tt = t - 1;
                if (brow < NOUT)
                    out[(size_t)tt * NOUT + brow] = fast_tanh(o);
                else
                    out[(size_t)T * NOUT + tt] = fast_sigmoid(o);
            }
        }

        grid_sync_flag(++bar);   // h_new(t) globally visible
    }

    // ---- final Stage B for step T-1 ----
    if (brow >= 0) {
        const float* hf = g_h[T & 1];
        const uint4* wr = (const uint4*)(g_wout_h + (size_t)brow * HDIM);
        const float4* h4 = (const float4*)hf;
        float acc = 0.f;
#pragma unroll 4
        for (int k = lane; k < HDIM / 8; k += 32) {
            uint4 u = wr[k];
            acc += dot8(u, h4[2 * k], h4[2 * k + 1]);
        }
        acc = warp_sum(acc);
        if (lane == 0) {
            float o = acc + c_bo;
            int tt = T - 1;
            if (brow < NOUT)
                out[(size_t)tt * NOUT + brow] = fast_tanh(o);
            else
                out[(size_t)T * NOUT + tt] = fast_sigmoid(o);
        }
    }
}

extern "C" void kernel_launch(void* const* d_in, const int* in_sizes, int n_in,
                              void* d_out, int out_size) {
    (void)in_sizes; (void)out_size;

    int dev = 0;
    cudaGetDevice(&dev);
    int sm = 148;
    cudaDeviceGetAttribute(&sm, cudaDevAttrMultiProcessorCount, dev);
    if (sm < 1) sm = 148;
    if (sm > MAXBLK) sm = MAXBLK;

    const float* start = (const float*)d_in[0];
    const float* enc   = (const float*)d_in[1];
    const float* W_ih  = (const float*)d_in[2];
    const float* W_hh  = (const float*)d_in[3];
    const float* b_ih  = (const float*)d_in[4];
    const float* b_hh  = (const float*)d_in[5];
    const float* W_out = (const float*)d_in[6];
    const float* b_out = (const float*)d_in[7];
    const int* maxlen  = (n_in > 8) ? (const int*)d_in[8] : nullptr;

    decoder_persistent_kernel<<<sm, NTHREADS>>>(
        start, enc, W_ih, W_hh, b_ih, b_hh, W_out, b_out, maxlen, (float*)d_out);
}

// round 9
// speedup vs baseline: 1.4029x; 1.4029x over previous
#include <cuda_runtime.h>
#include <cuda_fp16.h>
#include <cstdint>

// GRU decoder, H=4096, T=2048. Persistent single kernel + software grid barrier.
// R2: fp16 weight scratch (100.7 MB) -> L2-resident working set.
// R6: compiler-batched loads + fast approx gates + deferred Stage-B. [25.40 ms]
// R7/R8 lessons: cp.async ring and flag barrier both regressed -> reverted.
// R9: pin 8 of 28 warps' weights (192 KB) in persistent SMEM once per launch.
//     Those warps read weights via LDS only -> global weight traffic -28.6%,
//     L1tex/L2 queue relief for the 20 streaming warps.

#define HDIM 4096
#define IN_DIM 400
#define OROWS 401
#define NOUT 400
#define WARPS_PER_BLOCK 28
#define NTHREADS (WARPS_PER_BLOCK * 32)
#define PINNED_WARPS 8

#define SMEM_H_BYTES (HDIM * 4)                                  // 16384
#define PIN_HALVES (PINNED_WARPS * 3 * HDIM)                     // 98304 halves
#define SMEM_TOTAL (SMEM_H_BYTES + PIN_HALVES * 2)               // 212992 B

__device__ __half g_whh_h[(size_t)3 * HDIM * HDIM];   // 100.7 MB fp16 W_hh
__device__ __half g_wout_h[(size_t)OROWS * HDIM];     // 3.3 MB fp16 W_out
__device__ float g_h[2][HDIM];                        // double-buffered hidden state
__device__ float g_gx[3 * HDIM];                      // W_ih @ relu(x) + b_ih
__device__ unsigned g_cnt;
__device__ unsigned g_gen;

__device__ __forceinline__ float warp_sum(float v) {
#pragma unroll
    for (int o = 16; o; o >>= 1) v += __shfl_xor_sync(0xffffffffu, v, o);
    return v;
}

// Sense-reversing grid barrier; all blocks co-resident (grid == #SMs, 1 blk/SM).
__device__ __forceinline__ void grid_sync() {
    __syncthreads();
    if (threadIdx.x == 0) {
        __threadfence();
        unsigned gen = *(volatile unsigned*)&g_gen;
        unsigned nblk = gridDim.x;
        if (atomicAdd(&g_cnt, 1u) == nblk - 1u) {
            atomicExch(&g_cnt, 0u);
            __threadfence();
            atomicAdd(&g_gen, 1u);
        } else {
            while (*(volatile unsigned*)&g_gen == gen) { __nanosleep(32); }
        }
        __threadfence();
    }
    __syncthreads();
}

__device__ __forceinline__ float fast_sigmoid(float x) {
    float e;
    asm("ex2.approx.f32 %0, %1;" : "=f"(e) : "f"(-1.4426950408889634f * x));
    float r;
    asm("rcp.approx.f32 %0, %1;" : "=f"(r) : "f"(1.0f + e));
    return r;
}
__device__ __forceinline__ float fast_tanh(float x) {
    float r;
    asm("tanh.approx.f32 %0, %1;" : "=f"(r) : "f"(x));
    return r;
}

// dot of 8 fp16 weights (as uint4) with 8 fp32 h values, fp32 accumulate
__device__ __forceinline__ float dot8(uint4 u, float4 hA, float4 hB) {
    float2 p; float s0 = 0.f, s1 = 0.f;
    p = __half22float2(*(const __half2*)&u.x); s0 += p.x * hA.x; s1 += p.y * hA.y;
    p = __half22float2(*(const __half2*)&u.y); s0 += p.x * hA.z; s1 += p.y * hA.w;
    p = __half22float2(*(const __half2*)&u.z); s0 += p.x * hB.x; s1 += p.y * hB.y;
    p = __half22float2(*(const __half2*)&u.w); s0 += p.x * hB.z; s1 += p.y * hB.w;
    return s0 + s1;
}

__global__ void __launch_bounds__(NTHREADS, 1)
decoder_persistent_kernel(const float* __restrict__ start,
                          const float* __restrict__ enc,
                          const float* __restrict__ W_ih,
                          const float* __restrict__ W_hh,
                          const float* __restrict__ b_ih,
                          const float* __restrict__ b_hh,
                          const float* __restrict__ W_out,
                          const float* __restrict__ b_out,
                          const int*   __restrict__ maxlen_ptr,
                          float* __restrict__ out)
{
    extern __shared__ char smem_dyn[];
    float*  h_s   = (float*)smem_dyn;                       // 16 KB
    __half* pin_w = (__half*)(smem_dyn + SMEM_H_BYTES);     // 192 KB

    const int lane   = threadIdx.x & 31;
    const int warp   = threadIdx.x >> 5;
    const int gwarp  = blockIdx.x * WARPS_PER_BLOCK + warp;
    const int gwarps = gridDim.x * WARPS_PER_BLOCK;
    const int gtid    = blockIdx.x * NTHREADS + threadIdx.x;
    const int gthreads = gridDim.x * NTHREADS;
    const int T = maxlen_ptr ? *maxlen_ptr : 2048;

    // ---- convert W_hh, W_out to fp16 scratch (every launch; deterministic) ----
    {
        const size_t total = (size_t)3 * HDIM * HDIM;
        for (size_t idx = (size_t)gtid * 4; idx < total; idx += (size_t)gthreads * 4) {
            float4 v = *(const float4*)(W_hh + idx);
            __half2* dst = (__half2*)(g_whh_h + idx);
            dst[0] = __floats2half2_rn(v.x, v.y);
            dst[1] = __floats2half2_rn(v.z, v.w);
        }
        const size_t ototal = (size_t)OROWS * HDIM;
        for (size_t idx = (size_t)gtid * 4; idx < ototal; idx += (size_t)gthreads * 4) {
            float4 v = *(const float4*)(W_out + idx);
            __half2* dst = (__half2*)(g_wout_h + idx);
            dst[0] = __floats2half2_rn(v.x, v.y);
            dst[1] = __floats2half2_rn(v.z, v.w);
        }
    }

    // ---- fill pinned smem weights for warps 0..PINNED_WARPS-1 (once) ----
    // layout: pin_w[w][gate][HDIM], row for warp w = blockIdx*28 + w
    for (int idx = threadIdx.x * 4; idx < PIN_HALVES; idx += NTHREADS * 4) {
        int w   = idx / (3 * HDIM);
        int rem = idx - w * 3 * HDIM;
        int g   = rem / HDIM;
        int col = rem - g * HDIM;
        int row = blockIdx.x * WARPS_PER_BLOCK + w;
        if (row < HDIM) {
            float4 v = *(const float4*)(W_hh + ((size_t)(g * HDIM + row)) * HDIM + col);
            __half2* dst = (__half2*)(pin_w + idx);
            dst[0] = __floats2half2_rn(v.x, v.y);
            dst[1] = __floats2half2_rn(v.z, v.w);
        }
    }

    // ---- init: h0 = encoder_hidden ----
    for (int idx = gtid; idx < HDIM; idx += gthreads)
        g_h[0][idx] = enc[idx];

    // ---- gx = W_ih @ relu(start) + b_ih (once per launch, fp32) ----
    for (int r = gwarp; r < 3 * HDIM; r += gwarps) {
        const float* wr = W_ih + (size_t)r * IN_DIM;
        float acc = 0.f;
        for (int k = lane; k < IN_DIM; k += 32) {
            float x = start[k];
            x = x > 0.f ? x : 0.f;
            acc += wr[k] * x;
        }
        acc = warp_sum(acc);
        if (lane == 0) g_gx[r] = acc + b_ih[r];
    }
    grid_sync();

    // Stage-B row mapping: spread 401 W_out rows evenly across all SMs
    int spread = gwarps / OROWS;
    if (spread < 1) spread = 1;
    int brow = -1;
    if ((gwarp % spread) == 0 && (gwarp / spread) < OROWS) brow = gwarp / spread;

    const int myrow = (gwarp < HDIM) ? gwarp : -1;

    // hoist per-row constants out of the time loop
    float c_br = 0.f, c_bz = 0.f, c_bn = 0.f, c_gr = 0.f, c_gz = 0.f, c_gn = 0.f;
    if (myrow >= 0) {
        c_br = b_hh[myrow];
        c_bz = b_hh[myrow + HDIM];
        c_bn = b_hh[myrow + 2 * HDIM];
        c_gr = g_gx[myrow];
        c_gz = g_gx[myrow + HDIM];
        c_gn = g_gx[myrow + 2 * HDIM];
    }
    const float c_bo = (brow >= 0) ? b_out[brow] : 0.f;

    const bool pinned = (warp < PINNED_WARPS);

    // row-dot triple: same body specializes for smem / global pointers
    auto row_dots = [&](const uint4* __restrict__ w0, const uint4* __restrict__ w1,
                        const uint4* __restrict__ w2, const float4* __restrict__ h4,
                        float& a0, float& a1, float& a2) {
#pragma unroll 8
        for (int k = lane; k < HDIM / 8; k += 32) {   // 16 iterations
            uint4 u0 = w0[k];
            uint4 u1 = w1[k];
            uint4 u2 = w2[k];
            float4 hA = h4[2 * k];
            float4 hB = h4[2 * k + 1];
            a0 += dot8(u0, hA, hB);
            a1 += dot8(u1, hA, hB);
            a2 += dot8(u2, hA, hB);
        }
    };

    // ---- main recurrence ----
    for (int t = 0; t < T; t++) {
        const float* __restrict__ hc = g_h[t & 1];
        float* __restrict__ hn = g_h[(t + 1) & 1];

        // stage h_cur into shared memory (vectorized, fully coalesced)
        {
            const float4* src = (const float4*)hc;
            float4* dst = (float4*)h_s;
            for (int idx = threadIdx.x; idx < HDIM / 4; idx += NTHREADS)
                dst[idx] = src[idx];
        }
        __syncthreads();

        // Stage A: one warp per output i
        if (myrow >= 0) {
            const float4* h4 = (const float4*)h_s;
            float a0 = 0.f, a1 = 0.f, a2 = 0.f;
            if (pinned) {
                const __half* sw = pin_w + (size_t)warp * 3 * HDIM;
                row_dots((const uint4*)sw,
                         (const uint4*)(sw + HDIM),
                         (const uint4*)(sw + 2 * HDIM), h4, a0, a1, a2);
            } else {
                row_dots((const uint4*)(g_whh_h + (size_t)myrow * HDIM),
                         (const uint4*)(g_whh_h + ((size_t)myrow + HDIM) * HDIM),
                         (const uint4*)(g_whh_h + ((size_t)myrow + 2 * HDIM) * HDIM),
                         h4, a0, a1, a2);
            }
            a0 = warp_sum(a0);
            a1 = warp_sum(a1);
            a2 = warp_sum(a2);
            float r = fast_sigmoid(c_gr + a0 + c_br);
            float z = fast_sigmoid(c_gz + a1 + c_bz);
            float n = fast_tanh(c_gn + r * (a2 + c_bn));
            if (lane == 0) {
                hn[myrow] = (1.f - z) * n + z * h_s[myrow];
            }
        }

        // Stage B (deferred, for step t-1): h_new(t-1) == h_s; pre-barrier.
        if (t > 0 && brow >= 0) {
            const uint4* wr = (const uint4*)(g_wout_h + (size_t)brow * HDIM);
            const float4* h4 = (const float4*)h_s;
            float acc = 0.f;
#pragma unroll 4
            for (int k = lane; k < HDIM / 8; k += 32) {
                uint4 u = wr[k];
                acc += dot8(u, h4[2 * k], h4[2 * k + 1]);
            }
            acc = warp_sum(acc);
            if (lane == 0) {
                float o = acc + c_bo;
                int tt = t - 1;
                if (brow < NOUT)
                    out[(size_t)tt * NOUT + brow] = fast_tanh(o);
                else
                    out[(size_t)T * NOUT + tt] = fast_sigmoid(o);
            }
        }

        grid_sync();   // h_new(t) globally visible
    }

    // ---- final Stage B for step T-1 ----
    if (brow >= 0) {
        const float* hf = g_h[T & 1];
        const uint4* wr = (const uint4*)(g_wout_h + (size_t)brow * HDIM);
        const float4* h4 = (const float4*)hf;
        float acc = 0.f;
#pragma unroll 4
        for (int k = lane; k < HDIM / 8; k += 32) {
            uint4 u = wr[k];
            acc += dot8(u, h4[2 * k], h4[2 * k + 1]);
        }
        acc = warp_sum(acc);
        if (lane == 0) {
            float o = acc + c_bo;
            int tt = T - 1;
            if (brow < NOUT)
                out[(size_t)tt * NOUT + brow] = fast_tanh(o);
            else
                out[(size_t)T * NOUT + tt] = fast_sigmoid(o);
        }
    }
}

extern "C" void kernel_launch(void* const* d_in, const int* in_sizes, int n_in,
                              void* d_out, int out_size) {
    (void)in_sizes; (void)out_size;

    int dev = 0;
    cudaGetDevice(&dev);
    int sm = 148;
    cudaDeviceGetAttribute(&sm, cudaDevAttrMultiProcessorCount, dev);
    if (sm < 1) sm = 148;
    if (sm > 512) sm = 512;

    cudaFuncSetAttribute(decoder_persistent_kernel,
                         cudaFuncAttributeMaxDynamicSharedMemorySize, SMEM_TOTAL);

    const float* start = (const float*)d_in[0];
    const float* enc   = (const float*)d_in[1];
    const float* W_ih  = (const float*)d_in[2];
    const float* W_hh  = (const float*)d_in[3];
    const float* b_ih  = (const float*)d_in[4];
    const float* b_hh  = (const float*)d_in[5];
    const float* W_out = (const float*)d_in[6];
    const float* b_out = (const float*)d_in[7];
    const int* maxlen  = (n_in > 8) ? (const int*)d_in[8] : nullptr;

    decoder_persistent_kernel<<<sm, NTHREADS, SMEM_TOTAL>>>(
        start, enc, W_ih, W_hh, b_ih, b_hh, W_out, b_out, maxlen, (float*)d_out);
}

// round 10
// speedup vs baseline: 1.7244x; 1.2292x over previous
#include <cuda_runtime.h>
#include <cuda_fp16.h>
#include <cstdint>

// GRU decoder, H=4096, T=2048. Persistent single kernel + software grid barrier.
// R2: fp16 weight scratch -> L2-resident.  R6: batched loads + fast gates.
// R9: 8 warps' weights pinned in SMEM -> DRAM ~0%, L1 became top pipe (62%).
// R10: h_s stored fp16 (halves h LDS traffic; 1 LDS feeds all 3 gate streams;
//      recurrent z*h term keeps exact fp32 h via a scalar global read),
//      PINNED_WARPS 8 -> 9 (216 KB pin + 8 KB h = 224 KB smem).

#define HDIM 4096
#define IN_DIM 400
#define OROWS 401
#define NOUT 400
#define WARPS_PER_BLOCK 28
#define NTHREADS (WARPS_PER_BLOCK * 32)
#define PINNED_WARPS 9

#define SMEM_H_BYTES (HDIM * 2)                                  // 8192 (fp16 h)
#define PIN_HALVES (PINNED_WARPS * 3 * HDIM)                     // 110592 halves
#define SMEM_TOTAL (SMEM_H_BYTES + PIN_HALVES * 2)               // 229376 B

__device__ __half g_whh_h[(size_t)3 * HDIM * HDIM];   // 100.7 MB fp16 W_hh
__device__ __half g_wout_h[(size_t)OROWS * HDIM];     // 3.3 MB fp16 W_out
__device__ float g_h[2][HDIM];                        // double-buffered hidden state
__device__ float g_gx[3 * HDIM];                      // W_ih @ relu(x) + b_ih
__device__ unsigned g_cnt;
__device__ unsigned g_gen;

__device__ __forceinline__ float warp_sum(float v) {
#pragma unroll
    for (int o = 16; o; o >>= 1) v += __shfl_xor_sync(0xffffffffu, v, o);
    return v;
}

// Sense-reversing grid barrier; all blocks co-resident (grid == #SMs, 1 blk/SM).
__device__ __forceinline__ void grid_sync() {
    __syncthreads();
    if (threadIdx.x == 0) {
        __threadfence();
        unsigned gen = *(volatile unsigned*)&g_gen;
        unsigned nblk = gridDim.x;
        if (atomicAdd(&g_cnt, 1u) == nblk - 1u) {
            atomicExch(&g_cnt, 0u);
            __threadfence();
            atomicAdd(&g_gen, 1u);
        } else {
            while (*(volatile unsigned*)&g_gen == gen) { __nanosleep(32); }
        }
        __threadfence();
    }
    __syncthreads();
}

__device__ __forceinline__ float fast_sigmoid(float x) {
    float e;
    asm("ex2.approx.f32 %0, %1;" : "=f"(e) : "f"(-1.4426950408889634f * x));
    float r;
    asm("rcp.approx.f32 %0, %1;" : "=f"(r) : "f"(1.0f + e));
    return r;
}
__device__ __forceinline__ float fast_tanh(float x) {
    float r;
    asm("tanh.approx.f32 %0, %1;" : "=f"(r) : "f"(x));
    return r;
}

// dot of 8 fp16 weights (uint4) with 8 fp32 h values given as 4 float2
__device__ __forceinline__ float dot8f(uint4 u, float2 h0, float2 h1,
                                       float2 h2, float2 h3) {
    float2 p; float s0 = 0.f, s1 = 0.f;
    p = __half22float2(*(const __half2*)&u.x); s0 += p.x * h0.x; s1 += p.y * h0.y;
    p = __half22float2(*(const __half2*)&u.y); s0 += p.x * h1.x; s1 += p.y * h1.y;
    p = __half22float2(*(const __half2*)&u.z); s0 += p.x * h2.x; s1 += p.y * h2.y;
    p = __half22float2(*(const __half2*)&u.w); s0 += p.x * h3.x; s1 += p.y * h3.y;
    return s0 + s1;
}

__global__ void __launch_bounds__(NTHREADS, 1)
decoder_persistent_kernel(const float* __restrict__ start,
                          const float* __restrict__ enc,
                          const float* __restrict__ W_ih,
                          const float* __restrict__ W_hh,
                          const float* __restrict__ b_ih,
                          const float* __restrict__ b_hh,
                          const float* __restrict__ W_out,
                          const float* __restrict__ b_out,
                          const int*   __restrict__ maxlen_ptr,
                          float* __restrict__ out)
{
    extern __shared__ char smem_dyn[];
    __half* h_sh  = (__half*)smem_dyn;                      // 8 KB fp16 h
    __half* pin_w = (__half*)(smem_dyn + SMEM_H_BYTES);     // 216 KB pinned W

    const int lane   = threadIdx.x & 31;
    const int warp   = threadIdx.x >> 5;
    const int gwarp  = blockIdx.x * WARPS_PER_BLOCK + warp;
    const int gwarps = gridDim.x * WARPS_PER_BLOCK;
    const int gtid    = blockIdx.x * NTHREADS + threadIdx.x;
    const int gthreads = gridDim.x * NTHREADS;
    const int T = maxlen_ptr ? *maxlen_ptr : 2048;

    // ---- convert W_hh, W_out to fp16 scratch (every launch; deterministic) ----
    {
        const size_t total = (size_t)3 * HDIM * HDIM;
        for (size_t idx = (size_t)gtid * 4; idx < total; idx += (size_t)gthreads * 4) {
            float4 v = *(const float4*)(W_hh + idx);
            __half2* dst = (__half2*)(g_whh_h + idx);
            dst[0] = __floats2half2_rn(v.x, v.y);
            dst[1] = __floats2half2_rn(v.z, v.w);
        }
        const size_t ototal = (size_t)OROWS * HDIM;
        for (size_t idx = (size_t)gtid * 4; idx < ototal; idx += (size_t)gthreads * 4) {
            float4 v = *(const float4*)(W_out + idx);
            __half2* dst = (__half2*)(g_wout_h + idx);
            dst[0] = __floats2half2_rn(v.x, v.y);
            dst[1] = __floats2half2_rn(v.z, v.w);
        }
    }

    // ---- fill pinned smem weights for warps 0..PINNED_WARPS-1 (once) ----
    for (int idx = threadIdx.x * 4; idx < PIN_HALVES; idx += NTHREADS * 4) {
        int w   = idx / (3 * HDIM);
        int rem = idx - w * 3 * HDIM;
        int g   = rem / HDIM;
        int col = rem - g * HDIM;
        int row = blockIdx.x * WARPS_PER_BLOCK + w;
        if (row < HDIM) {
            float4 v = *(const float4*)(W_hh + ((size_t)(g * HDIM + row)) * HDIM + col);
            __half2* dst = (__half2*)(pin_w + idx);
            dst[0] = __floats2half2_rn(v.x, v.y);
            dst[1] = __floats2half2_rn(v.z, v.w);
        }
    }

    // ---- init: h0 = encoder_hidden ----
    for (int idx = gtid; idx < HDIM; idx += gthreads)
        g_h[0][idx] = enc[idx];

    // ---- gx = W_ih @ relu(start) + b_ih (once per launch, fp32) ----
    for (int r = gwarp; r < 3 * HDIM; r += gwarps) {
        const float* wr = W_ih + (size_t)r * IN_DIM;
        float acc = 0.f;
        for (int k = lane; k < IN_DIM; k += 32) {
            float x = start[k];
            x = x > 0.f ? x : 0.f;
            acc += wr[k] * x;
        }
        acc = warp_sum(acc);
        if (lane == 0) g_gx[r] = acc + b_ih[r];
    }
    grid_sync();

    // Stage-B row mapping: spread 401 W_out rows evenly across all SMs
    int spread = gwarps / OROWS;
    if (spread < 1) spread = 1;
    int brow = -1;
    if ((gwarp % spread) == 0 && (gwarp / spread) < OROWS) brow = gwarp / spread;

    const int myrow = (gwarp < HDIM) ? gwarp : -1;

    // hoist per-row constants out of the time loop
    float c_br = 0.f, c_bz = 0.f, c_bn = 0.f, c_gr = 0.f, c_gz = 0.f, c_gn = 0.f;
    if (myrow >= 0) {
        c_br = b_hh[myrow];
        c_bz = b_hh[myrow + HDIM];
        c_bn = b_hh[myrow + 2 * HDIM];
        c_gr = g_gx[myrow];
        c_gz = g_gx[myrow + HDIM];
        c_gn = g_gx[myrow + 2 * HDIM];
    }
    const float c_bo = (brow >= 0) ? b_out[brow] : 0.f;

    const bool pinned = (warp < PINNED_WARPS);

    // row-dot triple over fp16 h in smem (h unpacked once, reused by 3 streams)
    auto row_dots = [&](const uint4* __restrict__ w0, const uint4* __restrict__ w1,
                        const uint4* __restrict__ w2,
                        float& a0, float& a1, float& a2) {
        const uint4* hh = (const uint4*)h_sh;    // 512 chunks of 8 halves
#pragma unroll 8
        for (int k = lane; k < HDIM / 8; k += 32) {   // 16 iterations
            uint4 u0 = w0[k];
            uint4 u1 = w1[k];
            uint4 u2 = w2[k];
            uint4 hu = hh[k];
            float2 h0 = __half22float2(*(const __half2*)&hu.x);
            float2 h1 = __half22float2(*(const __half2*)&hu.y);
            float2 h2 = __half22float2(*(const __half2*)&hu.z);
            float2 h3 = __half22float2(*(const __half2*)&hu.w);
            a0 += dot8f(u0, h0, h1, h2, h3);
            a1 += dot8f(u1, h0, h1, h2, h3);
            a2 += dot8f(u2, h0, h1, h2, h3);
        }
    };

    // ---- main recurrence ----
    for (int t = 0; t < T; t++) {
        const float* __restrict__ hc = g_h[t & 1];
        float* __restrict__ hn = g_h[(t + 1) & 1];

        // exact fp32 h_old for the recurrent z*h term (issued early; L2 hit)
        float h_old = (myrow >= 0) ? hc[myrow] : 0.f;

        // stage h_cur into shared memory as fp16 (8 halves per thread)
        {
            const float4* src = (const float4*)hc;
            uint4* dst = (uint4*)h_sh;
            for (int idx = threadIdx.x; idx < HDIM / 8; idx += NTHREADS) {
                float4 a = src[2 * idx];
                float4 b = src[2 * idx + 1];
                uint4 o;
                *(__half2*)&o.x = __floats2half2_rn(a.x, a.y);
                *(__half2*)&o.y = __floats2half2_rn(a.z, a.w);
                *(__half2*)&o.z = __floats2half2_rn(b.x, b.y);
                *(__half2*)&o.w = __floats2half2_rn(b.z, b.w);
                dst[idx] = o;
            }
        }
        __syncthreads();

        // Stage A: one warp per output i
        if (myrow >= 0) {
            float a0 = 0.f, a1 = 0.f, a2 = 0.f;
            if (pinned) {
                const __half* sw = pin_w + (size_t)warp * 3 * HDIM;
                row_dots((const uint4*)sw,
                         (const uint4*)(sw + HDIM),
                         (const uint4*)(sw + 2 * HDIM), a0, a1, a2);
            } else {
                row_dots((const uint4*)(g_whh_h + (size_t)myrow * HDIM),
                         (const uint4*)(g_whh_h + ((size_t)myrow + HDIM) * HDIM),
                         (const uint4*)(g_whh_h + ((size_t)myrow + 2 * HDIM) * HDIM),
                         a0, a1, a2);
            }
            a0 = warp_sum(a0);
            a1 = warp_sum(a1);
            a2 = warp_sum(a2);
            float r = fast_sigmoid(c_gr + a0 + c_br);
            float z = fast_sigmoid(c_gz + a1 + c_bz);
            float n = fast_tanh(c_gn + r * (a2 + c_bn));
            if (lane == 0) {
                hn[myrow] = (1.f - z) * n + z * h_old;
            }
        }

        // Stage B (deferred, for step t-1): h_new(t-1) == h_sh; pre-barrier.
        if (t > 0 && brow >= 0) {
            const uint4* wr = (const uint4*)(g_wout_h + (size_t)brow * HDIM);
            const uint4* hh = (const uint4*)h_sh;
            float acc = 0.f;
#pragma unroll 4
            for (int k = lane; k < HDIM / 8; k += 32) {
                uint4 u = wr[k];
                uint4 hu = hh[k];
                float2 h0 = __half22float2(*(const __half2*)&hu.x);
                float2 h1 = __half22float2(*(const __half2*)&hu.y);
                float2 h2 = __half22float2(*(const __half2*)&hu.z);
                float2 h3 = __half22float2(*(const __half2*)&hu.w);
                acc += dot8f(u, h0, h1, h2, h3);
            }
            acc = warp_sum(acc);
            if (lane == 0) {
                float o = acc + c_bo;
                int tt = t - 1;
                if (brow < NOUT)
                    out[(size_t)tt * NOUT + brow] = fast_tanh(o);
                else
                    out[(size_t)T * NOUT + tt] = fast_sigmoid(o);
            }
        }

        grid_sync();   // h_new(t) globally visible
    }

    // ---- final Stage B for step T-1 (fp32 h from global; exactness fine) ----
    if (brow >= 0) {
        const float* hf = g_h[T & 1];
        const uint4* wr = (const uint4*)(g_wout_h + (size_t)brow * HDIM);
        float acc = 0.f;
#pragma unroll 4
        for (int k = lane; k < HDIM / 8; k += 32) {
            uint4 u = wr[k];
            const float4* hp = (const float4*)(hf + k * 8);
            float4 ha = hp[0], hb = hp[1];
            acc += dot8f(u, make_float2(ha.x, ha.y), make_float2(ha.z, ha.w),
                            make_float2(hb.x, hb.y), make_float2(hb.z, hb.w));
        }
        acc = warp_sum(acc);
        if (lane == 0) {
            float o = acc + c_bo;
            int tt = T - 1;
            if (brow < NOUT)
                out[(size_t)tt * NOUT + brow] = fast_tanh(o);
            else
                out[(size_t)T * NOUT + tt] = fast_sigmoid(o);
        }
    }
}

extern "C" void kernel_launch(void* const* d_in, const int* in_sizes, int n_in,
                              void* d_out, int out_size) {
    (void)in_sizes; (void)out_size;

    int dev = 0;
    cudaGetDevice(&dev);
    int sm = 148;
    cudaDeviceGetAttribute(&sm, cudaDevAttrMultiProcessorCount, dev);
    if (sm < 1) sm = 148;
    if (sm > 512) sm = 512;

    cudaFuncSetAttribute(decoder_persistent_kernel,
                         cudaFuncAttributeMaxDynamicSharedMemorySize, SMEM_TOTAL);

    const float* start = (const float*)d_in[0];
    const float* enc   = (const float*)d_in[1];
    const float* W_ih  = (const float*)d_in[2];
    const float* W_hh  = (const float*)d_in[3];
    const float* b_ih  = (const float*)d_in[4];
    const float* b_hh  = (const float*)d_in[5];
    const float* W_out = (const float*)d_in[6];
    const float* b_out = (const float*)d_in[7];
    const int* maxlen  = (n_in > 8) ? (const int*)d_in[8] : nullptr;

    decoder_persistent_kernel<<<sm, NTHREADS, SMEM_TOTAL>>>(
        start, enc, W_ih, W_hh, b_ih, b_hh, W_out, b_out, maxlen, (float*)d_out);
}